// round 6
// baseline (speedup 1.0000x reference)
#include <cuda_runtime.h>
#include <cstdint>

#define Bdim 8
#define Ndim 512
#define Pdim 16
#define Cdim 512
#define HD   64
#define BN   (Bdim*Ndim)
#define BNP  (BN*Pdim)
#define BH   (Bdim*8)
#define EP   (HD*Pdim)

#define OFF_XQ 0ull
#define OFF_XK (OFF_XQ + (size_t)BN*Cdim)
#define OFF_Q  (OFF_XK + (size_t)BN*Cdim)
#define OFF_K  (OFF_Q  + (size_t)BN*Cdim)
#define OFF_V  (OFF_K  + (size_t)BN*Cdim)
#define OFF_VP (OFF_V  + (size_t)BNP*Cdim)
#define OFF_S  (OFF_VP + (size_t)BNP*Cdim)
#define OFF_O2 (OFF_S  + (size_t)BH*Ndim*Ndim)
#define OFF_O  (OFF_O2 + (size_t)BNP*Cdim)
#define SCRATCH_FLOATS (OFF_O + (size_t)BNP*Cdim)

__device__ float g_scratch[SCRATCH_FLOATS];

__device__ __forceinline__ uint32_t f2tf(float f) {
    uint32_t u;
    asm("cvt.rna.tf32.f32 %0, %1;" : "=r"(u) : "f"(f));
    return u;
}
__device__ __forceinline__ float f2tff(float f) { return __uint_as_float(f2tf(f)); }

// ---------------- prep ----------------------------------------------------
__global__ void prep_kernel(const float* __restrict__ x,
                            const float* __restrict__ mask,
                            float* __restrict__ xq, float* __restrict__ xk) {
    int bn = blockIdx.x, c = threadIdx.x;
    const float* xb = x + (size_t)bn * Pdim * Cdim;
    const float* mb = mask + (size_t)bn * Pdim;
    float cnt = 0.f, s = 0.f;
#pragma unroll
    for (int p = 0; p < Pdim; p++) {
        float m = mb[p];
        cnt += m;
        s += m * xb[(size_t)p * Cdim + c];
    }
    xq[(size_t)bn * Cdim + c] = xb[c];
    xk[(size_t)bn * Cdim + c] = s / cnt;
}

// ---------------- tf32 GEMM, 128x256 CTA tile, BK=16, 8 warps of 64x64 -----
// Record layouts (validated in round 4):
//  A rec (16B) = (mb*2+ks)*32 + 4*gA + (tig ^ (gA&3) ^ ks); comps hi + 2*khi
//  B rec (16B) = nb*32 + 4*gn + (((gn>>1)+u)&3); comps = k in {u,u+4,u+8,u+12}
// BT=1: logical B[k][n] = Bm[n*ldb + k].
template<int BT>
__global__ void __launch_bounds__(256, 1)
tg_kernel(const float* __restrict__ A, int lda, size_t sAb, size_t sAh,
          const float* __restrict__ Bm, int ldb, size_t sBb, size_t sBh,
          float* __restrict__ Cm, int ldc, size_t sCb, size_t sCh,
          int K, float alpha, const float* __restrict__ bias) {
    const int zb = blockIdx.z >> 3, zh = blockIdx.z & 7;
    A  += (size_t)zb * sAb + (size_t)zh * sAh;
    Bm += (size_t)zb * sBb + (size_t)zh * sBh;
    Cm += (size_t)zb * sCb + (size_t)zh * sCh;

    __shared__ float4 smA[2][512];    // 16KB  (128 rows x 16 k per stage)
    __shared__ float4 smB[2][1024];   // 32KB  (256 cols x 16 k per stage)

    const int tid = threadIdx.x;
    const int lane = tid & 31, warp = tid >> 5;
    const int g = lane >> 2, tig = lane & 3;
    const int wmb = (warp >> 2) * 4;   // m-block base (units of 16)
    const int wnb = (warp & 3) * 8;    // n-block base (units of 8)
    const size_t row0 = (size_t)blockIdx.y * 128;
    const int col0 = blockIdx.x * 256;

    float acc[4][8][4];
#pragma unroll
    for (int mi = 0; mi < 4; mi++)
#pragma unroll
        for (int ni = 0; ni < 8; ni++)
#pragma unroll
            for (int r = 0; r < 4; r++) acc[mi][ni][r] = 0.f;

    // A ldg: thread -> row a_m, k-half a_ks (cols a_ks*8 .. +7)
    const int a_m = tid >> 1, a_ks = tid & 1;
    const float* Arow = A + (row0 + a_m) * (size_t)lda + a_ks * 8;

    // B ldg (non-BT): u = tid&3 -> k rows {u,u+4,u+8,u+12}; n-quad (tid>>2)*4
    const int bu = tid & 3, bq = tid >> 2;
    const float* Brow = BT ? (Bm + (size_t)(col0 + tid) * ldb)
                           : (Bm + (size_t)bu * ldb + col0 + bq * 4);

    float4 aR0, aR1;
    float4 bR[4];

#define LDG_AB(k0)                                                           \
    {                                                                        \
        aR0 = *(const float4*)(Arow + (k0));                                 \
        aR1 = *(const float4*)(Arow + (k0) + 4);                             \
        if (BT) {                                                            \
            _Pragma("unroll")                                                \
            for (int j = 0; j < 4; j++)                                      \
                bR[j] = *(const float4*)(Brow + (k0) + 4 * j);               \
        } else {                                                             \
            _Pragma("unroll")                                                \
            for (int j = 0; j < 4; j++)                                      \
                bR[j] = *(const float4*)(Brow + (size_t)((k0) + 4 * j) * ldb); \
        }                                                                    \
    }

#define STS_AB(st)                                                           \
    {                                                                        \
        float* as_ = (float*)smA[st];                                        \
        float av[8] = {aR0.x, aR0.y, aR0.z, aR0.w,                           \
                       aR1.x, aR1.y, aR1.z, aR1.w};                          \
        int mb = a_m >> 4, gA = a_m & 7, hi = (a_m >> 3) & 1;                \
        _Pragma("unroll")                                                    \
        for (int j = 0; j < 8; j++) {                                        \
            int slot = (j & 3) ^ (gA & 3) ^ a_ks;                            \
            int rec = (mb * 2 + a_ks) * 32 + 4 * gA + slot;                  \
            as_[rec * 4 + hi + 2 * (j >> 2)] = f2tff(av[j]);                 \
        }                                                                    \
        if (BT) {                                                            \
            float bv[16] = {bR[0].x, bR[0].y, bR[0].z, bR[0].w,              \
                            bR[1].x, bR[1].y, bR[1].z, bR[1].w,              \
                            bR[2].x, bR[2].y, bR[2].z, bR[2].w,              \
                            bR[3].x, bR[3].y, bR[3].z, bR[3].w};             \
            int nb = tid >> 3, gB = tid & 7;                                 \
            _Pragma("unroll")                                                \
            for (int tc = 0; tc < 4; tc++) {                                 \
                int slot = ((gB >> 1) + tc) & 3;                             \
                float4 v;                                                    \
                v.x = f2tff(bv[tc]);     v.y = f2tff(bv[tc + 4]);            \
                v.z = f2tff(bv[tc + 8]); v.w = f2tff(bv[tc + 12]);           \
                smB[st][nb * 32 + 4 * gB + slot] = v;                        \
            }                                                                \
        } else {                                                             \
            _Pragma("unroll")                                                \
            for (int e = 0; e < 4; e++) {                                    \
                int n_loc = bq * 4 + e;                                      \
                int nb = n_loc >> 3, gn = n_loc & 7;                         \
                int slot = ((gn >> 1) + bu) & 3;                             \
                float4 v;                                                    \
                const float* b0 = (const float*)&bR[0];                      \
                const float* b1 = (const float*)&bR[1];                      \
                const float* b2 = (const float*)&bR[2];                      \
                const float* b3 = (const float*)&bR[3];                      \
                v.x = f2tff(b0[e]); v.y = f2tff(b1[e]);                      \
                v.z = f2tff(b2[e]); v.w = f2tff(b3[e]);                      \
                smB[st][nb * 32 + 4 * gn + slot] = v;                        \
            }                                                                \
        }                                                                    \
    }

    LDG_AB(0);
    STS_AB(0);
    __syncthreads();

    const int K16 = K >> 4;
    for (int it = 0; it < K16; it++) {
        const int st = it & 1;
        const float4* as_ = smA[st];
        const float4* bs_ = smB[st];

        uint32_t bf[8][4];
        const int slotB = ((g >> 1) + tig) & 3;
#pragma unroll
        for (int ni = 0; ni < 8; ni++) {
            float4 v = bs_[(wnb + ni) * 32 + 4 * g + slotB];
            bf[ni][0] = __float_as_uint(v.x); bf[ni][1] = __float_as_uint(v.y);
            bf[ni][2] = __float_as_uint(v.z); bf[ni][3] = __float_as_uint(v.w);
        }

        const bool more = (it + 1 < K16);
        if (more) LDG_AB((it + 1) * 16);

#pragma unroll
        for (int ks = 0; ks < 2; ks++) {
            uint32_t af[4][4];
            const int slotA = tig ^ (g & 3) ^ ks;
#pragma unroll
            for (int mi = 0; mi < 4; mi++) {
                float4 v = as_[((wmb + mi) * 2 + ks) * 32 + 4 * g + slotA];
                af[mi][0] = __float_as_uint(v.x); af[mi][1] = __float_as_uint(v.y);
                af[mi][2] = __float_as_uint(v.z); af[mi][3] = __float_as_uint(v.w);
            }
#pragma unroll
            for (int mi = 0; mi < 4; mi++)
#pragma unroll
                for (int ni = 0; ni < 8; ni++) {
                    asm volatile(
                        "mma.sync.aligned.m16n8k8.row.col.f32.tf32.tf32.f32 "
                        "{%0,%1,%2,%3}, {%4,%5,%6,%7}, {%8,%9}, {%0,%1,%2,%3};"
                        : "+f"(acc[mi][ni][0]), "+f"(acc[mi][ni][1]),
                          "+f"(acc[mi][ni][2]), "+f"(acc[mi][ni][3])
                        : "r"(af[mi][0]), "r"(af[mi][1]),
                          "r"(af[mi][2]), "r"(af[mi][3]),
                          "r"(bf[ni][2 * ks]), "r"(bf[ni][2 * ks + 1]));
                }
        }
        if (more) STS_AB(st ^ 1);
        __syncthreads();
    }

#pragma unroll
    for (int mi = 0; mi < 4; mi++) {
        size_t r = row0 + (wmb + mi) * 16 + g;
#pragma unroll
        for (int ni = 0; ni < 8; ni++) {
            int c = col0 + (wnb + ni) * 8 + tig * 2;
            float bx = 0.f, by = 0.f;
            if (bias) { bx = bias[c]; by = bias[c + 1]; }
            *(float2*)&Cm[r * ldc + c] =
                make_float2(acc[mi][ni][0] * alpha + bx, acc[mi][ni][1] * alpha + by);
            *(float2*)&Cm[(r + 8) * ldc + c] =
                make_float2(acc[mi][ni][2] * alpha + bx, acc[mi][ni][3] * alpha + by);
        }
    }
}

// ---------------- softmax (rows of 512) -----------------------------------
__global__ void __launch_bounds__(256)
softmax_kernel(float* __restrict__ S) {
    float* r = S + (size_t)blockIdx.x * Ndim;
    int tid = threadIdx.x;
    float v0 = r[tid], v1 = r[tid + 256];
    __shared__ float red[8];
    unsigned full = 0xffffffffu;
    float m = fmaxf(v0, v1);
#pragma unroll
    for (int o = 16; o; o >>= 1) m = fmaxf(m, __shfl_xor_sync(full, m, o));
    if ((tid & 31) == 0) red[tid >> 5] = m;
    __syncthreads();
    float mm = fmaxf(fmaxf(fmaxf(red[0], red[1]), fmaxf(red[2], red[3])),
                     fmaxf(fmaxf(red[4], red[5]), fmaxf(red[6], red[7])));
    __syncthreads();
    float e0 = __expf(v0 - mm), e1 = __expf(v1 - mm);
    float s = e0 + e1;
#pragma unroll
    for (int o = 16; o; o >>= 1) s += __shfl_xor_sync(full, s, o);
    if ((tid & 31) == 0) red[tid >> 5] = s;
    __syncthreads();
    float inv = 1.0f / (red[0]+red[1]+red[2]+red[3]+red[4]+red[5]+red[6]+red[7]);
    r[tid] = e0 * inv;
    r[tid + 256] = e1 * inv;
}

// ---------------- pack V: Vp[bh, m, d*16+p] = V[b, m, p, h*64+d] ----------
__global__ void __launch_bounds__(256)
packV_kernel(const float* __restrict__ V, float* __restrict__ Vp) {
    int blk = blockIdx.x;
    int m = blk & 511, bh = blk >> 9;
    int b = bh >> 3, h = bh & 7;
    const float* src = V + (size_t)(b * Ndim + m) * Pdim * Cdim + h * HD;
    float* dst = Vp + (size_t)blk * EP;
    __shared__ float tile[Pdim][HD];
    int tid = threadIdx.x;
    int p = tid >> 4, d = (tid & 15) * 4;
    float4 v = *(const float4*)&src[(size_t)p * Cdim + d];
    tile[p][d] = v.x; tile[p][d+1] = v.y; tile[p][d+2] = v.z; tile[p][d+3] = v.w;
    __syncthreads();
    int e0 = tid * 4;
    float4 o;
    o.x = tile[(e0+0) & 15][(e0+0) >> 4];
    o.y = tile[(e0+1) & 15][(e0+1) >> 4];
    o.z = tile[(e0+2) & 15][(e0+2) >> 4];
    o.w = tile[(e0+3) & 15][(e0+3) >> 4];
    *(float4*)&dst[e0] = o;
}

// ---------------- unpack O: O[b,n,p,h*64+d] = O2[bh][n][d*16+p] -----------
__global__ void __launch_bounds__(256)
unpackO_kernel(const float* __restrict__ O2, float* __restrict__ O) {
    int blk = blockIdx.x;
    int n = blk & 511, bh = blk >> 9;
    int b = bh >> 3, h = bh & 7;
    const float* src = O2 + (size_t)blk * EP;
    float* dst = O + (size_t)(b * Ndim + n) * Pdim * Cdim + h * HD;
    __shared__ float tile[EP];
    int tid = threadIdx.x;
    *(float4*)&tile[tid * 4] = *(const float4*)&src[tid * 4];
    __syncthreads();
    int p = tid >> 4, d = (tid & 15) * 4;
    float4 o;
    o.x = tile[(d+0) * 16 + p];
    o.y = tile[(d+1) * 16 + p];
    o.z = tile[(d+2) * 16 + p];
    o.w = tile[(d+3) * 16 + p];
    *(float4*)&dst[(size_t)p * Cdim + d] = o;
}

// ---------------------------------------------------------------------------
extern "C" void kernel_launch(void* const* d_in, const int* in_sizes, int n_in,
                              void* d_out, int out_size) {
    const float* x     = (const float*)d_in[0];
    const float* mask  = (const float*)d_in[1];
    const float* Wqkv  = (const float*)d_in[4];
    const float* Wproj = (const float*)d_in[5];
    const float* bproj = (const float*)d_in[6];
    float* out = (float*)d_out;

    float* sc = nullptr;
    cudaGetSymbolAddress((void**)&sc, g_scratch);
    float* xq = sc + OFF_XQ;
    float* xk = sc + OFF_XK;
    float* Qb = sc + OFF_Q;
    float* Vb = sc + OFF_V;
    float* Vp = sc + OFF_VP;
    float* Sb = sc + OFF_S;
    float* O2 = sc + OFF_O2;
    float* Ob = sc + OFF_O;

    const size_t sNC = (size_t)BN * Cdim;
    const size_t sNN = (size_t)Ndim * Ndim;
    const size_t sNE = (size_t)Ndim * EP;

    // 1. prep
    prep_kernel<<<BN, Cdim>>>(x, mask, xq, xk);

    // 2. Q and K fused over z (z=0: xq@Wq, z=1: xk@Wk)
    tg_kernel<0><<<dim3(2, 32, 2), 256>>>(
        xq, Cdim, 0, sNC, Wqkv, 3 * Cdim, 0, 512, Qb, Cdim, 0, sNC,
        Cdim, 1.f, nullptr);

    // 3. V = x @ Wv
    tg_kernel<0><<<dim3(2, BNP / 128, 1), 256>>>(
        x, Cdim, 0, 0, Wqkv + 2 * Cdim, 3 * Cdim, 0, 0, Vb, Cdim, 0, 0,
        Cdim, 1.f, nullptr);

    // 4. pack V
    packV_kernel<<<BH * Ndim, 256>>>(Vb, Vp);

    // 5. scores: S = 0.125 * Q @ K^T  (BT mode, K=64)
    tg_kernel<1><<<dim3(2, 4, BH), 256>>>(
        Qb, Cdim, (size_t)Ndim * Cdim, HD,
        Qb + sNC, Cdim, (size_t)Ndim * Cdim, HD,
        Sb, Ndim, 8 * sNN, sNN,
        HD, 0.125f, nullptr);

    // 6. softmax
    softmax_kernel<<<BH * Ndim, 256>>>(Sb);

    // 7. O2 = S @ Vp  (batched 64, K=512)
    tg_kernel<0><<<dim3(4, 4, BH), 256>>>(
        Sb, Ndim, 8 * sNN, sNN,
        Vp, EP, 8 * sNE, sNE,
        O2, EP, 8 * sNE, sNE,
        Ndim, 1.f, nullptr);

    // 8. unpack O2
    unpackO_kernel<<<BH * Ndim, 256>>>(O2, Ob);

    // 9. proj
    tg_kernel<0><<<dim3(2, BNP / 128, 1), 256>>>(
        Ob, Cdim, 0, 0, Wproj, Cdim, 0, 0, out, Cdim, 0, 0,
        Cdim, 1.f, bproj);
}

// round 7
// speedup vs baseline: 1.0091x; 1.0091x over previous
#include <cuda_runtime.h>
#include <cstdint>

#define Bdim 8
#define Ndim 512
#define Pdim 16
#define Cdim 512
#define HD   64
#define BN   (Bdim*Ndim)
#define BNP  (BN*Pdim)
#define BH   (Bdim*8)
#define EP   (HD*Pdim)

#define OFF_XQ 0ull
#define OFF_XK (OFF_XQ + (size_t)BN*Cdim)
#define OFF_Q  (OFF_XK + (size_t)BN*Cdim)
#define OFF_K  (OFF_Q  + (size_t)BN*Cdim)
#define OFF_V  (OFF_K  + (size_t)BN*Cdim)
#define OFF_S  (OFF_V  + (size_t)BNP*Cdim)
#define OFF_O2 (OFF_S  + (size_t)BH*Ndim*Ndim)
#define SCRATCH_FLOATS (OFF_O2 + (size_t)BNP*Cdim)

__device__ float g_scratch[SCRATCH_FLOATS];

__device__ __forceinline__ uint32_t f2tf(float f) {
    uint32_t u;
    asm("cvt.rna.tf32.f32 %0, %1;" : "=r"(u) : "f"(f));
    return u;
}
__device__ __forceinline__ float f2tff(float f) { return __uint_as_float(f2tf(f)); }

// ---------------- prep ----------------------------------------------------
__global__ void prep_kernel(const float* __restrict__ x,
                            const float* __restrict__ mask,
                            float* __restrict__ xq, float* __restrict__ xk) {
    int bn = blockIdx.x, c = threadIdx.x;
    const float* xb = x + (size_t)bn * Pdim * Cdim;
    const float* mb = mask + (size_t)bn * Pdim;
    float cnt = 0.f, s = 0.f;
#pragma unroll
    for (int p = 0; p < Pdim; p++) {
        float m = mb[p];
        cnt += m;
        s += m * xb[(size_t)p * Cdim + c];
    }
    xq[(size_t)bn * Cdim + c] = xb[c];
    xk[(size_t)bn * Cdim + c] = s / cnt;
}

// ---------------- tf32 GEMM, 128x128 CTA tile, BK=16, 8 warps of 64x32 -----
// Record layouts (validated in rounds 4/6):
//  A rec (16B) = (mb*2+ks)*32 + 4*gA + ((j&3)^(gA&3)^ks); comps hi + 2*(j>>2)
//  B rec (16B) = nb*32 + 4*gn + (((gn>>1)+u)&3); comps = k in {u,u+4,u+8,u+12}
// AM: 0 = A row-major [M,K];  1 = gather from O2[bh][n][p*64+d]
// BM: 0 = B row-major [K,N];  1 = gather from V (n = p*64+d);  2 = B[k][n]=Bm[n*ldb+k]
template<int AM, int BM>
__global__ void __launch_bounds__(256, 2)
tg_kernel(const float* __restrict__ A, int lda, size_t sAb, size_t sAh,
          const float* __restrict__ Bm, int ldb, size_t sBb, size_t sBh,
          float* __restrict__ Cm, int ldc, size_t sCb, size_t sCh,
          int K, float alpha, const float* __restrict__ bias) {
    const int zb = blockIdx.z >> 3, zh = blockIdx.z & 7;
    A  += (size_t)zb * sAb + (size_t)zh * sAh;
    Bm += (size_t)zb * sBb + (size_t)zh * sBh;
    Cm += (size_t)zb * sCb + (size_t)zh * sCh;

    __shared__ float4 smA[2][512];    // 16KB (128 m x 16 k per stage)
    __shared__ float4 smB[2][512];    // 16KB (128 n x 16 k per stage)

    const int tid = threadIdx.x;
    const int lane = tid & 31, warp = tid >> 5;
    const int g = lane >> 2, tig = lane & 3;
    const int wmb = (warp >> 2) * 4;   // m-block base (units of 16)
    const int wnb = (warp & 3) * 4;    // n-block base (units of 8)
    const size_t row0 = (size_t)blockIdx.y * 128;
    const int col0 = blockIdx.x * 128;

    float acc[4][4][4];
#pragma unroll
    for (int mi = 0; mi < 4; mi++)
#pragma unroll
        for (int ni = 0; ni < 4; ni++)
#pragma unroll
            for (int r = 0; r < 4; r++) acc[mi][ni][r] = 0.f;

    // ---- A ldg: thread -> row a_m, k-half a_ks ----
    const int a_m = tid >> 1, a_ks = tid & 1;
    const float* Arow;
    size_t ga_base = 0;
    if (AM == 0) {
        Arow = A + (row0 + a_m) * (size_t)lda + a_ks * 8;
    } else {
        size_t row = row0 + a_m;
        int ab = (int)(row >> 13), an = (int)(row >> 4) & 511, ap = (int)row & 15;
        // base for h=0,d=0: O2[((ab*8 + h)*512 + an)*1024 + ap*64 + d]
        ga_base = (((size_t)ab * 8) * 512 + an) * 1024 + ap * 64;
        Arow = A;  // unused offset form
    }

    // ---- B ldg assignments ----
    const int bu = tid & 3, bnq = (tid >> 2) & 31, bdup = tid >> 7;   // BM 0/1
    const int tn = tid & 127, tkh = tid >> 7;                        // BM 2

    float4 aR0, aR1, bR0, bR1;

    auto ldgA = [&](int k0) {
        if (AM == 0) {
            aR0 = *(const float4*)(Arow + k0);
            aR1 = *(const float4*)(Arow + k0 + 4);
        } else {
            int kb = k0 + a_ks * 8;
            int h = kb >> 6, d = kb & 63;
            const float* p0 = A + ga_base + (size_t)h * (512 * 1024) + d;
            aR0 = *(const float4*)p0;
            aR1 = *(const float4*)(p0 + 4);
        }
    };
    auto ldgB = [&](int k0) {
        if (BM == 0) {
            bR0 = *(const float4*)(Bm + (size_t)(k0 + bu + 8 * bdup) * ldb + col0 + bnq * 4);
            bR1 = *(const float4*)(Bm + (size_t)(k0 + bu + 4 + 8 * bdup) * ldb + col0 + bnq * 4);
        } else if (BM == 1) {
            int n = col0 + bnq * 4;
            int pp = n >> 6, dd = n & 63;
            int k0r = k0 + bu + 8 * bdup;
            bR0 = *(const float4*)(Bm + ((size_t)k0r * 16 + pp) * 512 + dd);
            bR1 = *(const float4*)(Bm + ((size_t)(k0r + 4) * 16 + pp) * 512 + dd);
        } else {
            const float* bc = Bm + (size_t)(col0 + tn) * ldb + k0 + 8 * tkh;
            bR0 = *(const float4*)bc;
            bR1 = *(const float4*)(bc + 4);
        }
    };
    auto stsAB = [&](int st) {
        float* as_ = (float*)smA[st];
        float av[8] = {aR0.x, aR0.y, aR0.z, aR0.w, aR1.x, aR1.y, aR1.z, aR1.w};
        int mb = a_m >> 4, gA = a_m & 7, hi = (a_m >> 3) & 1;
#pragma unroll
        for (int j = 0; j < 8; j++) {
            int slot = (j & 3) ^ (gA & 3) ^ a_ks;
            int rec = (mb * 2 + a_ks) * 32 + 4 * gA + slot;
            as_[rec * 4 + hi + 2 * (j >> 2)] = f2tff(av[j]);
        }
        if (BM < 2) {
            const float* b0 = (const float*)&bR0;
            const float* b1 = (const float*)&bR1;
#pragma unroll
            for (int e = 0; e < 4; e++) {
                int n_loc = bnq * 4 + e;
                int nb = n_loc >> 3, gn = n_loc & 7;
                int slot = ((gn >> 1) + bu) & 3;
                float2* r = (float2*)&smB[st][nb * 32 + 4 * gn + slot];
                r[bdup] = make_float2(f2tff(b0[e]), f2tff(b1[e]));
            }
        } else {
            float v[8] = {bR0.x, bR0.y, bR0.z, bR0.w, bR1.x, bR1.y, bR1.z, bR1.w};
            int nb = tn >> 3, gn = tn & 7;
#pragma unroll
            for (int u2 = 0; u2 < 4; u2++) {
                int slot = ((gn >> 1) + u2) & 3;
                float2* r = (float2*)&smB[st][nb * 32 + 4 * gn + slot];
                r[tkh] = make_float2(f2tff(v[u2]), f2tff(v[u2 + 4]));
            }
        }
    };

    ldgA(0); ldgB(0);
    stsAB(0);
    __syncthreads();

    const int K16 = K >> 4;
    for (int it = 0; it < K16; it++) {
        const int st = it & 1;
        const float4* as_ = smA[st];
        const float4* bs_ = smB[st];

        uint32_t bf[4][4];
        const int slotB = ((g >> 1) + tig) & 3;
#pragma unroll
        for (int ni = 0; ni < 4; ni++) {
            float4 v = bs_[(wnb + ni) * 32 + 4 * g + slotB];
            bf[ni][0] = __float_as_uint(v.x); bf[ni][1] = __float_as_uint(v.y);
            bf[ni][2] = __float_as_uint(v.z); bf[ni][3] = __float_as_uint(v.w);
        }

        const bool more = (it + 1 < K16);
        if (more) { ldgA((it + 1) * 16); ldgB((it + 1) * 16); }

#pragma unroll
        for (int ks = 0; ks < 2; ks++) {
            uint32_t af[4][4];
            const int slotA = tig ^ (g & 3) ^ ks;
#pragma unroll
            for (int mi = 0; mi < 4; mi++) {
                float4 v = as_[((wmb + mi) * 2 + ks) * 32 + 4 * g + slotA];
                af[mi][0] = __float_as_uint(v.x); af[mi][1] = __float_as_uint(v.y);
                af[mi][2] = __float_as_uint(v.z); af[mi][3] = __float_as_uint(v.w);
            }
#pragma unroll
            for (int mi = 0; mi < 4; mi++)
#pragma unroll
                for (int ni = 0; ni < 4; ni++) {
                    asm volatile(
                        "mma.sync.aligned.m16n8k8.row.col.f32.tf32.tf32.f32 "
                        "{%0,%1,%2,%3}, {%4,%5,%6,%7}, {%8,%9}, {%0,%1,%2,%3};"
                        : "+f"(acc[mi][ni][0]), "+f"(acc[mi][ni][1]),
                          "+f"(acc[mi][ni][2]), "+f"(acc[mi][ni][3])
                        : "r"(af[mi][0]), "r"(af[mi][1]),
                          "r"(af[mi][2]), "r"(af[mi][3]),
                          "r"(bf[ni][2 * ks]), "r"(bf[ni][2 * ks + 1]));
                }
        }
        if (more) stsAB(st ^ 1);
        __syncthreads();
    }

#pragma unroll
    for (int mi = 0; mi < 4; mi++) {
        size_t r = row0 + (wmb + mi) * 16 + g;
#pragma unroll
        for (int ni = 0; ni < 4; ni++) {
            int c = col0 + (wnb + ni) * 8 + tig * 2;
            float bx = 0.f, by = 0.f;
            if (bias) { bx = bias[c]; by = bias[c + 1]; }
            *(float2*)&Cm[r * ldc + c] =
                make_float2(acc[mi][ni][0] * alpha + bx, acc[mi][ni][1] * alpha + by);
            *(float2*)&Cm[(r + 8) * ldc + c] =
                make_float2(acc[mi][ni][2] * alpha + bx, acc[mi][ni][3] * alpha + by);
        }
    }
}

// ---------------- softmax (rows of 512) -----------------------------------
__global__ void __launch_bounds__(256)
softmax_kernel(float* __restrict__ S) {
    float* r = S + (size_t)blockIdx.x * Ndim;
    int tid = threadIdx.x;
    float v0 = r[tid], v1 = r[tid + 256];
    __shared__ float red[8];
    unsigned full = 0xffffffffu;
    float m = fmaxf(v0, v1);
#pragma unroll
    for (int o = 16; o; o >>= 1) m = fmaxf(m, __shfl_xor_sync(full, m, o));
    if ((tid & 31) == 0) red[tid >> 5] = m;
    __syncthreads();
    float mm = fmaxf(fmaxf(fmaxf(red[0], red[1]), fmaxf(red[2], red[3])),
                     fmaxf(fmaxf(red[4], red[5]), fmaxf(red[6], red[7])));
    __syncthreads();
    float e0 = __expf(v0 - mm), e1 = __expf(v1 - mm);
    float s = e0 + e1;
#pragma unroll
    for (int o = 16; o; o >>= 1) s += __shfl_xor_sync(full, s, o);
    if ((tid & 31) == 0) red[tid >> 5] = s;
    __syncthreads();
    float inv = 1.0f / (red[0]+red[1]+red[2]+red[3]+red[4]+red[5]+red[6]+red[7]);
    r[tid] = e0 * inv;
    r[tid + 256] = e1 * inv;
}

// ---------------------------------------------------------------------------
extern "C" void kernel_launch(void* const* d_in, const int* in_sizes, int n_in,
                              void* d_out, int out_size) {
    const float* x     = (const float*)d_in[0];
    const float* mask  = (const float*)d_in[1];
    const float* Wqkv  = (const float*)d_in[4];
    const float* Wproj = (const float*)d_in[5];
    const float* bproj = (const float*)d_in[6];
    float* out = (float*)d_out;

    float* sc = nullptr;
    cudaGetSymbolAddress((void**)&sc, g_scratch);
    float* xq = sc + OFF_XQ;
    float* xk = sc + OFF_XK;
    float* Qb = sc + OFF_Q;
    float* Kb = sc + OFF_K;
    float* Vb = sc + OFF_V;
    float* Sb = sc + OFF_S;
    float* O2 = sc + OFF_O2;

    const size_t sNC = (size_t)BN * Cdim;        // 2097152
    const size_t sNN = (size_t)Ndim * Ndim;      // 262144
    const size_t sNE = (size_t)Ndim * EP;        // 524288
    const size_t sVB = (size_t)Ndim * Pdim * Cdim; // V b-stride 4194304

    // 1. prep
    prep_kernel<<<BN, Cdim>>>(x, mask, xq, xk);

    // 2. Q and K fused over z (z=0: xq@Wq, z=1: xk@Wk)
    tg_kernel<0,0><<<dim3(4, 32, 2), 256>>>(
        xq, Cdim, 0, sNC, Wqkv, 3 * Cdim, 0, 512, Qb, Cdim, 0, sNC,
        Cdim, 1.f, nullptr);

    // 3. V = x @ Wv
    tg_kernel<0,0><<<dim3(4, BNP / 128, 1), 256>>>(
        x, Cdim, 0, 0, Wqkv + 2 * Cdim, 3 * Cdim, 0, 0, Vb, Cdim, 0, 0,
        Cdim, 1.f, nullptr);

    // 4. scores: S = 0.125 * Q @ K^T  (BT mode, K=64, per bh)
    tg_kernel<0,2><<<dim3(4, 4, BH), 256>>>(
        Qb, Cdim, (size_t)Ndim * Cdim, HD,
        Kb, Cdim, (size_t)Ndim * Cdim, HD,
        Sb, Ndim, 8 * sNN, sNN,
        HD, 0.125f, nullptr);

    // 5. softmax
    softmax_kernel<<<BH * Ndim, 256>>>(Sb);

    // 6. O2[bh][n][p*64+d] = S @ Vgather  (K=512, N=1024, per bh)
    tg_kernel<0,1><<<dim3(8, 4, BH), 256>>>(
        Sb, Ndim, 8 * sNN, sNN,
        Vb, 0, sVB, (size_t)HD,
        O2, EP, 8 * sNE, sNE,
        Ndim, 1.f, nullptr);

    // 7. proj: out = Ogather @ Wproj + bproj
    tg_kernel<1,0><<<dim3(4, BNP / 128, 1), 256>>>(
        O2, 0, 0, 0, Wproj, Cdim, 0, 0, out, Cdim, 0, 0,
        Cdim, 1.f, bproj);
}

// round 8
// speedup vs baseline: 1.2702x; 1.2587x over previous
#include <cuda_runtime.h>
#include <cstdint>

#define Bdim 8
#define Ndim 512
#define Pdim 16
#define Cdim 512
#define HD   64
#define BN   (Bdim*Ndim)
#define BNP  (BN*Pdim)
#define BH   (Bdim*8)
#define EP   (HD*Pdim)

#define OFF_XQ 0ull
#define OFF_XK (OFF_XQ + (size_t)BN*Cdim)
#define OFF_Q  (OFF_XK + (size_t)BN*Cdim)
#define OFF_K  (OFF_Q  + (size_t)BN*Cdim)
#define OFF_V  (OFF_K  + (size_t)BN*Cdim)
#define OFF_S  (OFF_V  + (size_t)BNP*Cdim)
#define OFF_O2 (OFF_S  + (size_t)BH*Ndim*Ndim)
#define SCRATCH_FLOATS (OFF_O2 + (size_t)BNP*Cdim)

__device__ float g_scratch[SCRATCH_FLOATS];

__device__ __forceinline__ uint32_t f2tf(float f) {
    uint32_t u;
    asm("cvt.rna.tf32.f32 %0, %1;" : "=r"(u) : "f"(f));
    return u;
}

// ---------------- prep ----------------------------------------------------
__global__ void prep_kernel(const float* __restrict__ x,
                            const float* __restrict__ mask,
                            float* __restrict__ xq, float* __restrict__ xk) {
    int bn = blockIdx.x, c = threadIdx.x;
    const float* xb = x + (size_t)bn * Pdim * Cdim;
    const float* mb = mask + (size_t)bn * Pdim;
    float cnt = 0.f, s = 0.f;
#pragma unroll
    for (int p = 0; p < Pdim; p++) {
        float m = mb[p];
        cnt += m;
        s += m * xb[(size_t)p * Cdim + c];
    }
    xq[(size_t)bn * Cdim + c] = xb[c];
    xk[(size_t)bn * Cdim + c] = s / cnt;
}

// ---------------- tf32 tensor GEMM (round-2 core, verbatim layouts) --------
// 128x128 tile, BK=32, 256 threads (8 warps, 2x4 grid, 64x32 warp tile).
// AM: 0 = A row-major [M,K];       1 = gather A from O2[bh][n][p*64+d]
// BM: 0 = B row-major [K,N];       1 = gather B[k=m][n=p*64+d] from V
//     2 = B[k][n] = Bm[n*ldb + k]  (transposed operand, for scores)
template<int AM, int BM>
__global__ void __launch_bounds__(256)
tgemm_kernel(const float* __restrict__ A, int lda, size_t sAb, size_t sAh,
             const float* __restrict__ Bm, int ldb, size_t sBb, size_t sBh,
             float* __restrict__ Cm, int ldc, size_t sCb, size_t sCh,
             int K, float alpha, const float* __restrict__ bias) {
    const int zb = blockIdx.z >> 3, zh = blockIdx.z & 7;
    A  += (size_t)zb * sAb + (size_t)zh * sAh;
    Bm += (size_t)zb * sBb + (size_t)zh * sBh;
    Cm += (size_t)zb * sCb + (size_t)zh * sCh;

    __shared__ uint32_t As[128][36];
    __shared__ uint32_t Bs[32][136];

    const int tid  = threadIdx.x;
    const int lane = tid & 31, warp = tid >> 5;
    const int g    = lane >> 2, tig = lane & 3;
    const int wm   = (warp >> 2) * 64;
    const int wn   = (warp & 3) * 32;
    const size_t row0 = (size_t)blockIdx.y * 128;
    const int col0 = blockIdx.x * 128;

    float acc[4][4][4];
#pragma unroll
    for (int mi = 0; mi < 4; mi++)
#pragma unroll
        for (int ni = 0; ni < 4; ni++)
#pragma unroll
            for (int r = 0; r < 4; r++) acc[mi][ni][r] = 0.f;

    const int ar = tid >> 3;        // 0..31 (+32*i)
    const int ac = (tid & 7) * 4;   // 0..28 within BK
    const int br = tid >> 3;        // k-row 0..31
    const int bc = (tid & 7) * 4;   // 0..28 (+32*i)
    // BT-mode staging assignment
    const int tn = tid & 127, tkh = tid >> 7;

    // A-gather row bases (fixed across k)
    size_t gaBase[4];
    if (AM == 1) {
#pragma unroll
        for (int i = 0; i < 4; i++) {
            size_t row = row0 + ar + 32 * i;
            int ab = (int)(row >> 13);
            int an = (int)(row >> 4) & 511;
            int ap = (int)row & 15;
            gaBase[i] = (((size_t)ab * 8) * 512 + an) * 1024 + (size_t)ap * 64;
        }
    }

    float4 aR[4], bR[4];

    auto ldgA = [&](int k0) {
#pragma unroll
        for (int i = 0; i < 4; i++) {
            if (AM == 0) {
                aR[i] = *(const float4*)(A + (row0 + ar + 32 * i) * lda + k0 + ac);
            } else {
                int k = k0 + ac;
                int h = k >> 6, d = k & 63;
                aR[i] = *(const float4*)(A + gaBase[i] + (size_t)h * (512 * 1024) + d);
            }
        }
    };
    auto ldgB = [&](int k0) {
        if (BM == 0) {
#pragma unroll
            for (int i = 0; i < 4; i++)
                bR[i] = *(const float4*)(Bm + (size_t)(k0 + br) * ldb + col0 + bc + 32 * i);
        } else if (BM == 1) {
#pragma unroll
            for (int i = 0; i < 4; i++) {
                int n = col0 + bc + 32 * i;
                int pp = n >> 6, dd = n & 63;
                bR[i] = *(const float4*)(Bm + ((size_t)(k0 + br) * 16 + pp) * 512 + dd);
            }
        } else {
            const float* bcol = Bm + (size_t)(col0 + tn) * ldb + k0 + 16 * tkh;
#pragma unroll
            for (int i = 0; i < 4; i++)
                bR[i] = *(const float4*)(bcol + 4 * i);
        }
    };
    auto stsAB = [&]() {
#pragma unroll
        for (int i = 0; i < 4; i++) {
            int r = ar + 32 * i;
            As[r][ac + 0] = f2tf(aR[i].x); As[r][ac + 1] = f2tf(aR[i].y);
            As[r][ac + 2] = f2tf(aR[i].z); As[r][ac + 3] = f2tf(aR[i].w);
        }
        if (BM < 2) {
#pragma unroll
            for (int i = 0; i < 4; i++) {
                int c = bc + 32 * i;
                Bs[br][c + 0] = f2tf(bR[i].x); Bs[br][c + 1] = f2tf(bR[i].y);
                Bs[br][c + 2] = f2tf(bR[i].z); Bs[br][c + 3] = f2tf(bR[i].w);
            }
        } else {
#pragma unroll
            for (int i = 0; i < 4; i++) {
                int k = 16 * tkh + 4 * i;
                Bs[k + 0][tn] = f2tf(bR[i].x); Bs[k + 1][tn] = f2tf(bR[i].y);
                Bs[k + 2][tn] = f2tf(bR[i].z); Bs[k + 3][tn] = f2tf(bR[i].w);
            }
        }
    };

    ldgA(0); ldgB(0);

    for (int k0 = 0; k0 < K; k0 += 32) {
        stsAB();
        __syncthreads();

        if (k0 + 32 < K) { ldgA(k0 + 32); ldgB(k0 + 32); }

#pragma unroll
        for (int ks = 0; ks < 4; ks++) {
            const int k8 = ks * 8;
            uint32_t a[4][4], b[4][2];
#pragma unroll
            for (int mi = 0; mi < 4; mi++) {
                int m = wm + mi * 16 + g;
                a[mi][0] = As[m][k8 + tig];
                a[mi][1] = As[m + 8][k8 + tig];
                a[mi][2] = As[m][k8 + tig + 4];
                a[mi][3] = As[m + 8][k8 + tig + 4];
            }
#pragma unroll
            for (int ni = 0; ni < 4; ni++) {
                int n = wn + ni * 8 + g;
                b[ni][0] = Bs[k8 + tig][n];
                b[ni][1] = Bs[k8 + tig + 4][n];
            }
#pragma unroll
            for (int mi = 0; mi < 4; mi++)
#pragma unroll
                for (int ni = 0; ni < 4; ni++) {
                    asm volatile(
                        "mma.sync.aligned.m16n8k8.row.col.f32.tf32.tf32.f32 "
                        "{%0,%1,%2,%3}, {%4,%5,%6,%7}, {%8,%9}, {%0,%1,%2,%3};"
                        : "+f"(acc[mi][ni][0]), "+f"(acc[mi][ni][1]),
                          "+f"(acc[mi][ni][2]), "+f"(acc[mi][ni][3])
                        : "r"(a[mi][0]), "r"(a[mi][1]), "r"(a[mi][2]), "r"(a[mi][3]),
                          "r"(b[ni][0]), "r"(b[ni][1]));
                }
        }
        __syncthreads();
    }

#pragma unroll
    for (int mi = 0; mi < 4; mi++) {
        size_t r = row0 + wm + mi * 16 + g;
#pragma unroll
        for (int ni = 0; ni < 4; ni++) {
            int c = col0 + wn + ni * 8 + tig * 2;
            float bx = 0.f, by = 0.f;
            if (bias) { bx = bias[c]; by = bias[c + 1]; }
            *(float2*)&Cm[r * ldc + c] =
                make_float2(acc[mi][ni][0] * alpha + bx, acc[mi][ni][1] * alpha + by);
            *(float2*)&Cm[(r + 8) * ldc + c] =
                make_float2(acc[mi][ni][2] * alpha + bx, acc[mi][ni][3] * alpha + by);
        }
    }
}

// ---------------- softmax (rows of 512) -----------------------------------
__global__ void __launch_bounds__(256)
softmax_kernel(float* __restrict__ S) {
    float* r = S + (size_t)blockIdx.x * Ndim;
    int tid = threadIdx.x;
    float v0 = r[tid], v1 = r[tid + 256];
    __shared__ float red[8];
    unsigned full = 0xffffffffu;
    float m = fmaxf(v0, v1);
#pragma unroll
    for (int o = 16; o; o >>= 1) m = fmaxf(m, __shfl_xor_sync(full, m, o));
    if ((tid & 31) == 0) red[tid >> 5] = m;
    __syncthreads();
    float mm = fmaxf(fmaxf(fmaxf(red[0], red[1]), fmaxf(red[2], red[3])),
                     fmaxf(fmaxf(red[4], red[5]), fmaxf(red[6], red[7])));
    __syncthreads();
    float e0 = __expf(v0 - mm), e1 = __expf(v1 - mm);
    float s = e0 + e1;
#pragma unroll
    for (int o = 16; o; o >>= 1) s += __shfl_xor_sync(full, s, o);
    if ((tid & 31) == 0) red[tid >> 5] = s;
    __syncthreads();
    float inv = 1.0f / (red[0]+red[1]+red[2]+red[3]+red[4]+red[5]+red[6]+red[7]);
    r[tid] = e0 * inv;
    r[tid + 256] = e1 * inv;
}

// ---------------------------------------------------------------------------
extern "C" void kernel_launch(void* const* d_in, const int* in_sizes, int n_in,
                              void* d_out, int out_size) {
    const float* x     = (const float*)d_in[0];
    const float* mask  = (const float*)d_in[1];
    const float* Wqkv  = (const float*)d_in[4];
    const float* Wproj = (const float*)d_in[5];
    const float* bproj = (const float*)d_in[6];
    float* out = (float*)d_out;

    float* sc = nullptr;
    cudaGetSymbolAddress((void**)&sc, g_scratch);
    float* xq = sc + OFF_XQ;
    float* xk = sc + OFF_XK;
    float* Qb = sc + OFF_Q;
    float* Kb = sc + OFF_K;
    float* Vb = sc + OFF_V;
    float* Sb = sc + OFF_S;
    float* O2 = sc + OFF_O2;

    const size_t sNC = (size_t)BN * Cdim;           // 2097152
    const size_t sNN = (size_t)Ndim * Ndim;         // 262144
    const size_t sNE = (size_t)Ndim * EP;           // 524288
    const size_t sVB = (size_t)Ndim * Pdim * Cdim;  // 4194304

    // 1. prep
    prep_kernel<<<BN, Cdim>>>(x, mask, xq, xk);

    // 2. Q and K fused (z=0: xq@Wq -> Qb, z=1: xk@Wk -> Kb)
    tgemm_kernel<0,0><<<dim3(4, 32, 2), 256>>>(
        xq, Cdim, 0, sNC, Wqkv, 3 * Cdim, 0, 512, Qb, Cdim, 0, sNC,
        Cdim, 1.f, nullptr);

    // 3. V = x @ Wv
    tgemm_kernel<0,0><<<dim3(4, BNP / 128, 1), 256>>>(
        x, Cdim, 0, 0, Wqkv + 2 * Cdim, 3 * Cdim, 0, 0, Vb, Cdim, 0, 0,
        Cdim, 1.f, nullptr);

    // 4. scores: S = 0.125 * Q @ K^T  (BT mode, K=64, per bh)
    tgemm_kernel<0,2><<<dim3(4, 4, BH), 256>>>(
        Qb, Cdim, (size_t)Ndim * Cdim, HD,
        Kb, Cdim, (size_t)Ndim * Cdim, HD,
        Sb, Ndim, 8 * sNN, sNN,
        HD, 0.125f, nullptr);

    // 5. softmax
    softmax_kernel<<<BH * Ndim, 256>>>(Sb);

    // 6. O2[bh][n][p*64+d] = S @ Vgather  (K=512, N=1024, per bh)
    tgemm_kernel<0,1><<<dim3(8, 4, BH), 256>>>(
        Sb, Ndim, 8 * sNN, sNN,
        Vb, 0, sVB, (size_t)HD,
        O2, EP, 8 * sNE, sNE,
        Ndim, 1.f, nullptr);

    // 7. proj: out = Ogather @ Wproj + bproj
    tgemm_kernel<1,0><<<dim3(4, BNP / 128, 1), 256>>>(
        O2, 0, 0, 0, Wproj, Cdim, 0, 0, out, Cdim, 0, 0,
        Cdim, 1.f, bproj);
}

// round 9
// speedup vs baseline: 1.3834x; 1.0891x over previous
#include <cuda_runtime.h>
#include <cstdint>

#define Bdim 8
#define Ndim 512
#define Pdim 16
#define Cdim 512
#define HD   64
#define BN   (Bdim*Ndim)
#define BNP  (BN*Pdim)
#define BH   (Bdim*8)
#define EP   (HD*Pdim)

#define OFF_XQ 0ull
#define OFF_XK (OFF_XQ + (size_t)BN*Cdim)
#define OFF_Q  (OFF_XK + (size_t)BN*Cdim)
#define OFF_K  (OFF_Q  + (size_t)BN*Cdim)
#define OFF_V  (OFF_K  + (size_t)BN*Cdim)
#define OFF_S  (OFF_V  + (size_t)BNP*Cdim)
#define OFF_O2 (OFF_S  + (size_t)BH*Ndim*Ndim)
#define SCRATCH_FLOATS (OFF_O2 + (size_t)BNP*Cdim)

__device__ float g_scratch[SCRATCH_FLOATS];

__device__ __forceinline__ uint32_t f2tf(float f) {
    uint32_t u;
    asm("cvt.rna.tf32.f32 %0, %1;" : "=r"(u) : "f"(f));
    return u;
}

// dynamic smem layout (uint32 words):
//   As stage s: [s*4608 .. +4608)   (128 rows x 36)
//   Bs stage s: [9216 + s*4352 ..)  (32 rows x 136)
#define ASTG 4608
#define BBASE 9216
#define BSTG 4352
#define SMEM_WORDS (BBASE + 2*BSTG)   /* 17920 words = 71680 B */

// ---------------- prep ----------------------------------------------------
__global__ void prep_kernel(const float* __restrict__ x,
                            const float* __restrict__ mask,
                            float* __restrict__ xq, float* __restrict__ xk) {
    int bn = blockIdx.x, c = threadIdx.x;
    const float* xb = x + (size_t)bn * Pdim * Cdim;
    const float* mb = mask + (size_t)bn * Pdim;
    float cnt = 0.f, s = 0.f;
#pragma unroll
    for (int p = 0; p < Pdim; p++) {
        float m = mb[p];
        cnt += m;
        s += m * xb[(size_t)p * Cdim + c];
    }
    xq[(size_t)bn * Cdim + c] = xb[c];
    xk[(size_t)bn * Cdim + c] = s / cnt;
}

// ---------------- tf32 tensor GEMM (r8 core + double-buffer, 1 sync/k0) ----
// 128x128 tile, BK=32, 256 threads (8 warps, 2x4 grid, 64x32 warp tile).
// AM: 0 = A row-major [M,K];       1 = gather A from O2[bh][n][p*64+d]
// BM: 0 = B row-major [K,N];       1 = gather B[k=m][n=p*64+d] from V
//     2 = B[k][n] = Bm[n*ldb + k]  (transposed operand, for scores)
template<int AM, int BM>
__global__ void __launch_bounds__(256, 2)
tgemm_kernel(const float* __restrict__ A, int lda, size_t sAb, size_t sAh,
             const float* __restrict__ Bm, int ldb, size_t sBb, size_t sBh,
             float* __restrict__ Cm, int ldc, size_t sCb, size_t sCh,
             int K, float alpha, const float* __restrict__ bias) {
    extern __shared__ uint32_t smw[];
    const int zb = blockIdx.z >> 3, zh = blockIdx.z & 7;
    A  += (size_t)zb * sAb + (size_t)zh * sAh;
    Bm += (size_t)zb * sBb + (size_t)zh * sBh;
    Cm += (size_t)zb * sCb + (size_t)zh * sCh;

    const int tid  = threadIdx.x;
    const int lane = tid & 31, warp = tid >> 5;
    const int g    = lane >> 2, tig = lane & 3;
    const int wm   = (warp >> 2) * 64;
    const int wn   = (warp & 3) * 32;
    const size_t row0 = (size_t)blockIdx.y * 128;
    const int col0 = blockIdx.x * 128;

    float acc[4][4][4];
#pragma unroll
    for (int mi = 0; mi < 4; mi++)
#pragma unroll
        for (int ni = 0; ni < 4; ni++)
#pragma unroll
            for (int r = 0; r < 4; r++) acc[mi][ni][r] = 0.f;

    const int ar = tid >> 3;        // 0..31 (+32*i)
    const int ac = (tid & 7) * 4;   // 0..28 within BK
    const int br = tid >> 3;        // k-row 0..31
    const int bc = (tid & 7) * 4;   // 0..28 (+32*i)
    const int tn = tid & 127, tkh = tid >> 7;   // BT staging

    size_t gaBase[4];
    if (AM == 1) {
#pragma unroll
        for (int i = 0; i < 4; i++) {
            size_t row = row0 + ar + 32 * i;
            int ab = (int)(row >> 13);
            int an = (int)(row >> 4) & 511;
            int ap = (int)row & 15;
            gaBase[i] = (((size_t)ab * 8) * 512 + an) * 1024 + (size_t)ap * 64;
        }
    }

    float4 aR[4], bR[4];

    auto ldgA = [&](int k0) {
#pragma unroll
        for (int i = 0; i < 4; i++) {
            if (AM == 0) {
                aR[i] = *(const float4*)(A + (row0 + ar + 32 * i) * lda + k0 + ac);
            } else {
                int k = k0 + ac;
                int h = k >> 6, d = k & 63;
                aR[i] = *(const float4*)(A + gaBase[i] + (size_t)h * (512 * 1024) + d);
            }
        }
    };
    auto ldgB = [&](int k0) {
        if (BM == 0) {
#pragma unroll
            for (int i = 0; i < 4; i++)
                bR[i] = *(const float4*)(Bm + (size_t)(k0 + br) * ldb + col0 + bc + 32 * i);
        } else if (BM == 1) {
#pragma unroll
            for (int i = 0; i < 4; i++) {
                int n = col0 + bc + 32 * i;
                int pp = n >> 6, dd = n & 63;
                bR[i] = *(const float4*)(Bm + ((size_t)(k0 + br) * 16 + pp) * 512 + dd);
            }
        } else {
            const float* bcol = Bm + (size_t)(col0 + tn) * ldb + k0 + 16 * tkh;
#pragma unroll
            for (int i = 0; i < 4; i++)
                bR[i] = *(const float4*)(bcol + 4 * i);
        }
    };
    auto stsAB = [&](int st) {
        uint32_t* As = smw + st * ASTG;
        uint32_t* Bs = smw + BBASE + st * BSTG;
#pragma unroll
        for (int i = 0; i < 4; i++) {
            int r = ar + 32 * i;
            As[r * 36 + ac + 0] = f2tf(aR[i].x); As[r * 36 + ac + 1] = f2tf(aR[i].y);
            As[r * 36 + ac + 2] = f2tf(aR[i].z); As[r * 36 + ac + 3] = f2tf(aR[i].w);
        }
        if (BM < 2) {
#pragma unroll
            for (int i = 0; i < 4; i++) {
                int c = bc + 32 * i;
                Bs[br * 136 + c + 0] = f2tf(bR[i].x); Bs[br * 136 + c + 1] = f2tf(bR[i].y);
                Bs[br * 136 + c + 2] = f2tf(bR[i].z); Bs[br * 136 + c + 3] = f2tf(bR[i].w);
            }
        } else {
#pragma unroll
            for (int i = 0; i < 4; i++) {
                int k = 16 * tkh + 4 * i;
                Bs[(k + 0) * 136 + tn] = f2tf(bR[i].x);
                Bs[(k + 1) * 136 + tn] = f2tf(bR[i].y);
                Bs[(k + 2) * 136 + tn] = f2tf(bR[i].z);
                Bs[(k + 3) * 136 + tn] = f2tf(bR[i].w);
            }
        }
    };

    ldgA(0); ldgB(0);
    stsAB(0);
    __syncthreads();

    const int K32 = K >> 5;
    for (int it = 0; it < K32; it++) {
        const int st = it & 1;
        const uint32_t* As = smw + st * ASTG;
        const uint32_t* Bs = smw + BBASE + st * BSTG;
        const bool more = (it + 1 < K32);

        if (more) { ldgA((it + 1) * 32); ldgB((it + 1) * 32); }

#pragma unroll
        for (int ks = 0; ks < 4; ks++) {
            const int k8 = ks * 8;
            uint32_t a[4][4], b[4][2];
#pragma unroll
            for (int mi = 0; mi < 4; mi++) {
                int m = wm + mi * 16 + g;
                a[mi][0] = As[m * 36 + k8 + tig];
                a[mi][1] = As[(m + 8) * 36 + k8 + tig];
                a[mi][2] = As[m * 36 + k8 + tig + 4];
                a[mi][3] = As[(m + 8) * 36 + k8 + tig + 4];
            }
#pragma unroll
            for (int ni = 0; ni < 4; ni++) {
                int n = wn + ni * 8 + g;
                b[ni][0] = Bs[(k8 + tig) * 136 + n];
                b[ni][1] = Bs[(k8 + tig + 4) * 136 + n];
            }
#pragma unroll
            for (int mi = 0; mi < 4; mi++)
#pragma unroll
                for (int ni = 0; ni < 4; ni++) {
                    asm volatile(
                        "mma.sync.aligned.m16n8k8.row.col.f32.tf32.tf32.f32 "
                        "{%0,%1,%2,%3}, {%4,%5,%6,%7}, {%8,%9}, {%0,%1,%2,%3};"
                        : "+f"(acc[mi][ni][0]), "+f"(acc[mi][ni][1]),
                          "+f"(acc[mi][ni][2]), "+f"(acc[mi][ni][3])
                        : "r"(a[mi][0]), "r"(a[mi][1]), "r"(a[mi][2]), "r"(a[mi][3]),
                          "r"(b[ni][0]), "r"(b[ni][1]));
                }
        }
        if (more) stsAB(st ^ 1);
        __syncthreads();
    }

#pragma unroll
    for (int mi = 0; mi < 4; mi++) {
        size_t r = row0 + wm + mi * 16 + g;
#pragma unroll
        for (int ni = 0; ni < 4; ni++) {
            int c = col0 + wn + ni * 8 + tig * 2;
            float bx = 0.f, by = 0.f;
            if (bias) { bx = bias[c]; by = bias[c + 1]; }
            *(float2*)&Cm[r * ldc + c] =
                make_float2(acc[mi][ni][0] * alpha + bx, acc[mi][ni][1] * alpha + by);
            *(float2*)&Cm[(r + 8) * ldc + c] =
                make_float2(acc[mi][ni][2] * alpha + bx, acc[mi][ni][3] * alpha + by);
        }
    }
}

// ---------------- softmax (rows of 512) -----------------------------------
__global__ void __launch_bounds__(256)
softmax_kernel(float* __restrict__ S) {
    float* r = S + (size_t)blockIdx.x * Ndim;
    int tid = threadIdx.x;
    float v0 = r[tid], v1 = r[tid + 256];
    __shared__ float red[8];
    unsigned full = 0xffffffffu;
    float m = fmaxf(v0, v1);
#pragma unroll
    for (int o = 16; o; o >>= 1) m = fmaxf(m, __shfl_xor_sync(full, m, o));
    if ((tid & 31) == 0) red[tid >> 5] = m;
    __syncthreads();
    float mm = fmaxf(fmaxf(fmaxf(red[0], red[1]), fmaxf(red[2], red[3])),
                     fmaxf(fmaxf(red[4], red[5]), fmaxf(red[6], red[7])));
    __syncthreads();
    float e0 = __expf(v0 - mm), e1 = __expf(v1 - mm);
    float s = e0 + e1;
#pragma unroll
    for (int o = 16; o; o >>= 1) s += __shfl_xor_sync(full, s, o);
    if ((tid & 31) == 0) red[tid >> 5] = s;
    __syncthreads();
    float inv = 1.0f / (red[0]+red[1]+red[2]+red[3]+red[4]+red[5]+red[6]+red[7]);
    r[tid] = e0 * inv;
    r[tid + 256] = e1 * inv;
}

// ---------------------------------------------------------------------------
extern "C" void kernel_launch(void* const* d_in, const int* in_sizes, int n_in,
                              void* d_out, int out_size) {
    const float* x     = (const float*)d_in[0];
    const float* mask  = (const float*)d_in[1];
    const float* Wqkv  = (const float*)d_in[4];
    const float* Wproj = (const float*)d_in[5];
    const float* bproj = (const float*)d_in[6];
    float* out = (float*)d_out;

    float* sc = nullptr;
    cudaGetSymbolAddress((void**)&sc, g_scratch);
    float* xq = sc + OFF_XQ;
    float* xk = sc + OFF_XK;
    float* Qb = sc + OFF_Q;
    float* Kb = sc + OFF_K;
    float* Vb = sc + OFF_V;
    float* Sb = sc + OFF_S;
    float* O2 = sc + OFF_O2;

    const size_t sNC = (size_t)BN * Cdim;           // 2097152
    const size_t sNN = (size_t)Ndim * Ndim;         // 262144
    const size_t sNE = (size_t)Ndim * EP;           // 524288
    const size_t sVB = (size_t)Ndim * Pdim * Cdim;  // 4194304
    const int SMB = SMEM_WORDS * 4;                 // 71680 B

    // opt-in to >48KB dynamic smem (host-side, idempotent, capture-safe)
    cudaFuncSetAttribute(tgemm_kernel<0,0>, cudaFuncAttributeMaxDynamicSharedMemorySize, SMB);
    cudaFuncSetAttribute(tgemm_kernel<0,1>, cudaFuncAttributeMaxDynamicSharedMemorySize, SMB);
    cudaFuncSetAttribute(tgemm_kernel<0,2>, cudaFuncAttributeMaxDynamicSharedMemorySize, SMB);
    cudaFuncSetAttribute(tgemm_kernel<1,0>, cudaFuncAttributeMaxDynamicSharedMemorySize, SMB);

    // 1. prep
    prep_kernel<<<BN, Cdim>>>(x, mask, xq, xk);

    // 2. Q and K fused (z=0: xq@Wq -> Qb, z=1: xk@Wk -> Kb)
    tgemm_kernel<0,0><<<dim3(4, 32, 2), 256, SMB>>>(
        xq, Cdim, 0, sNC, Wqkv, 3 * Cdim, 0, 512, Qb, Cdim, 0, sNC,
        Cdim, 1.f, nullptr);

    // 3. V = x @ Wv
    tgemm_kernel<0,0><<<dim3(4, BNP / 128, 1), 256, SMB>>>(
        x, Cdim, 0, 0, Wqkv + 2 * Cdim, 3 * Cdim, 0, 0, Vb, Cdim, 0, 0,
        Cdim, 1.f, nullptr);

    // 4. scores: S = 0.125 * Q @ K^T  (BT mode, K=64, per bh)
    tgemm_kernel<0,2><<<dim3(4, 4, BH), 256, SMB>>>(
        Qb, Cdim, (size_t)Ndim * Cdim, HD,
        Kb, Cdim, (size_t)Ndim * Cdim, HD,
        Sb, Ndim, 8 * sNN, sNN,
        HD, 0.125f, nullptr);

    // 5. softmax
    softmax_kernel<<<BH * Ndim, 256>>>(Sb);

    // 6. O2[bh][n][p*64+d] = S @ Vgather  (K=512, N=1024, per bh)
    tgemm_kernel<0,1><<<dim3(8, 4, BH), 256, SMB>>>(
        Sb, Ndim, 8 * sNN, sNN,
        Vb, 0, sVB, (size_t)HD,
        O2, EP, 8 * sNE, sNE,
        Ndim, 1.f, nullptr);

    // 7. proj: out = Ogather @ Wproj + bproj
    tgemm_kernel<1,0><<<dim3(4, BNP / 128, 1), 256, SMB>>>(
        O2, 0, 0, 0, Wproj, Cdim, 0, 0, out, Cdim, 0, 0,
        Cdim, 1.f, bproj);
}

// round 10
// speedup vs baseline: 1.5119x; 1.0929x over previous
#include <cuda_runtime.h>
#include <cstdint>

#define Bdim 8
#define Ndim 512
#define Pdim 16
#define Cdim 512
#define HD   64
#define BN   (Bdim*Ndim)
#define BNP  (BN*Pdim)
#define BH   (Bdim*8)
#define EP   (HD*Pdim)

#define OFF_XQ 0ull
#define OFF_XK (OFF_XQ + (size_t)BN*Cdim)
#define OFF_Q  (OFF_XK + (size_t)BN*Cdim)
#define OFF_K  (OFF_Q  + (size_t)BN*Cdim)
#define OFF_V  (OFF_K  + (size_t)BN*Cdim)
#define OFF_S  (OFF_V  + (size_t)BNP*Cdim)
#define OFF_O2 (OFF_S  + (size_t)BH*Ndim*Ndim)
#define OFF_XC (OFF_O2 + (size_t)BNP*Cdim)
#define OFF_WC (OFF_XC + (size_t)BNP*Cdim)
#define OFF_WP (OFF_WC + (size_t)Cdim*3*Cdim)
#define SCRATCH_FLOATS (OFF_WP + (size_t)Cdim*Cdim)

__device__ float g_scratch[SCRATCH_FLOATS];

__device__ __forceinline__ uint32_t f2tf(float f) {
    uint32_t u;
    asm("cvt.rna.tf32.f32 %0, %1;" : "=r"(u) : "f"(f));
    return u;
}
__device__ __forceinline__ float f2tff(float f) { return __uint_as_float(f2tf(f)); }

__device__ __forceinline__ void cp16(uint32_t dst, const void* src) {
    asm volatile("cp.async.ca.shared.global [%0], [%1], 16;" :: "r"(dst), "l"(src));
}
__device__ __forceinline__ void cp_commit() {
    asm volatile("cp.async.commit_group;");
}
__device__ __forceinline__ void cp_wait0() {
    asm volatile("cp.async.wait_group 0;");
}

// dynamic smem layout (uint32 words):
//   As stage s: [s*4608 .. +4608)   (128 rows x 36; row stride 144B, 16B-aligned)
//   Bs stage s: [9216 + s*4352 ..)  (32 rows x 136; row stride 544B, 16B-aligned)
#define ASTG 4608
#define BBASE 9216
#define BSTG 4352
#define SMEM_WORDS (BBASE + 2*BSTG)   /* 71680 B */

// ---------------- prep: xq/xk (tf32-rounded) + converted copy of x ---------
__global__ void prep_kernel(const float* __restrict__ x,
                            const float* __restrict__ mask,
                            float* __restrict__ xq, float* __restrict__ xk,
                            float* __restrict__ xc) {
    int bn = blockIdx.x, c = threadIdx.x;
    const float* xb = x + (size_t)bn * Pdim * Cdim;
    float* xcb = xc + (size_t)bn * Pdim * Cdim;
    const float* mb = mask + (size_t)bn * Pdim;
    float cnt = 0.f, s = 0.f;
#pragma unroll
    for (int p = 0; p < Pdim; p++) {
        float m = mb[p];
        float v = xb[(size_t)p * Cdim + c];
        cnt += m;
        s += m * v;
        xcb[(size_t)p * Cdim + c] = f2tff(v);
    }
    xq[(size_t)bn * Cdim + c] = f2tff(xb[c]);
    xk[(size_t)bn * Cdim + c] = f2tff(s / cnt);
}

// ---------------- elementwise tf32 convert copy ----------------------------
__global__ void cvt_copy_kernel(const float* __restrict__ src,
                                float* __restrict__ dst, int n) {
    int i = blockIdx.x * 256 + threadIdx.x;
    if (i < n) dst[i] = f2tff(src[i]);
}

// ---------------- tf32 tensor GEMM, cp.async staging -----------------------
// 128x128 tile, BK=32, 256 threads (8 warps, 2x4 grid, 64x32 warp tile).
// All operands must be PRE-ROUNDED to tf32 (cvt at producers).
// AM: 0 = A row-major [M,K];       1 = gather A from O2[bh][n][p*64+d]
// BM: 0 = B row-major [K,N];       1 = gather B[k=m][n=p*64+d] from V
//     2 = B[k][n] = Bm[n*ldb + k]  (transposed; legacy LDG+cvt staging)
template<int AM, int BM>
__global__ void __launch_bounds__(256, 2)
tgemm_kernel(const float* __restrict__ A, int lda, size_t sAb, size_t sAh,
             const float* __restrict__ Bm, int ldb, size_t sBb, size_t sBh,
             float* __restrict__ Cm, int ldc, size_t sCb, size_t sCh,
             int K, float alpha, const float* __restrict__ bias, int cvt_out) {
    extern __shared__ uint32_t smw[];
    const uint32_t sbase = (uint32_t)__cvta_generic_to_shared(smw);
    const int zb = blockIdx.z >> 3, zh = blockIdx.z & 7;
    A  += (size_t)zb * sAb + (size_t)zh * sAh;
    Bm += (size_t)zb * sBb + (size_t)zh * sBh;
    Cm += (size_t)zb * sCb + (size_t)zh * sCh;

    const int tid  = threadIdx.x;
    const int lane = tid & 31, warp = tid >> 5;
    const int g    = lane >> 2, tig = lane & 3;
    const int wm   = (warp >> 2) * 64;
    const int wn   = (warp & 3) * 32;
    const size_t row0 = (size_t)blockIdx.y * 128;
    const int col0 = blockIdx.x * 128;

    float acc[4][4][4];
#pragma unroll
    for (int mi = 0; mi < 4; mi++)
#pragma unroll
        for (int ni = 0; ni < 4; ni++)
#pragma unroll
            for (int r = 0; r < 4; r++) acc[mi][ni][r] = 0.f;

    const int ar = tid >> 3;        // 0..31 (+32*i)
    const int ac = (tid & 7) * 4;   // 0..28 within BK
    const int br = tid >> 3;        // k-row 0..31
    const int bc = (tid & 7) * 4;   // 0..28 (+32*i)
    const int tn = tid & 127, tkh = tid >> 7;   // BT staging

    size_t gaBase[4];
    if (AM == 1) {
#pragma unroll
        for (int i = 0; i < 4; i++) {
            size_t row = row0 + ar + 32 * i;
            int ab = (int)(row >> 13);
            int an = (int)(row >> 4) & 511;
            int ap = (int)row & 15;
            gaBase[i] = (((size_t)ab * 8) * 512 + an) * 1024 + (size_t)ap * 64;
        }
    }

    auto copyA = [&](int st, int k0) {
        uint32_t d0 = sbase + (st * ASTG) * 4;
#pragma unroll
        for (int i = 0; i < 4; i++) {
            uint32_t dst = d0 + ((ar + 32 * i) * 36 + ac) * 4;
            const float* src;
            if (AM == 0) {
                src = A + (row0 + ar + 32 * i) * lda + k0 + ac;
            } else {
                int k = k0 + ac;
                int h = k >> 6, d = k & 63;
                src = A + gaBase[i] + (size_t)h * (512 * 1024) + d;
            }
            cp16(dst, src);
        }
    };
    auto copyB = [&](int st, int k0) {
        uint32_t d0 = sbase + (BBASE + st * BSTG) * 4;
        if (BM == 0) {
#pragma unroll
            for (int i = 0; i < 4; i++)
                cp16(d0 + (br * 136 + bc + 32 * i) * 4,
                     Bm + (size_t)(k0 + br) * ldb + col0 + bc + 32 * i);
        } else if (BM == 1) {
#pragma unroll
            for (int i = 0; i < 4; i++) {
                int n = col0 + bc + 32 * i;
                int pp = n >> 6, dd = n & 63;
                cp16(d0 + (br * 136 + bc + 32 * i) * 4,
                     Bm + ((size_t)(k0 + br) * 16 + pp) * 512 + dd);
            }
        } else {
            uint32_t* Bs = smw + BBASE + st * BSTG;
            const float* bcol = Bm + (size_t)(col0 + tn) * ldb + k0 + 16 * tkh;
#pragma unroll
            for (int i = 0; i < 4; i++) {
                float4 v = *(const float4*)(bcol + 4 * i);
                int k = 16 * tkh + 4 * i;
                Bs[(k + 0) * 136 + tn] = f2tf(v.x);
                Bs[(k + 1) * 136 + tn] = f2tf(v.y);
                Bs[(k + 2) * 136 + tn] = f2tf(v.z);
                Bs[(k + 3) * 136 + tn] = f2tf(v.w);
            }
        }
    };

    copyA(0, 0); copyB(0, 0);
    cp_commit();

    const int K32 = K >> 5;
    for (int it = 0; it < K32; it++) {
        const int st = it & 1;
        cp_wait0();
        __syncthreads();

        const bool more = (it + 1 < K32);
        if (more) { copyA(st ^ 1, (it + 1) * 32); copyB(st ^ 1, (it + 1) * 32); }
        cp_commit();

        const uint32_t* As = smw + st * ASTG;
        const uint32_t* Bs = smw + BBASE + st * BSTG;
#pragma unroll
        for (int ks = 0; ks < 4; ks++) {
            const int k8 = ks * 8;
            uint32_t a[4][4], b[4][2];
#pragma unroll
            for (int mi = 0; mi < 4; mi++) {
                int m = wm + mi * 16 + g;
                a[mi][0] = As[m * 36 + k8 + tig];
                a[mi][1] = As[(m + 8) * 36 + k8 + tig];
                a[mi][2] = As[m * 36 + k8 + tig + 4];
                a[mi][3] = As[(m + 8) * 36 + k8 + tig + 4];
            }
#pragma unroll
            for (int ni = 0; ni < 4; ni++) {
                int n = wn + ni * 8 + g;
                b[ni][0] = Bs[(k8 + tig) * 136 + n];
                b[ni][1] = Bs[(k8 + tig + 4) * 136 + n];
            }
#pragma unroll
            for (int mi = 0; mi < 4; mi++)
#pragma unroll
                for (int ni = 0; ni < 4; ni++) {
                    asm volatile(
                        "mma.sync.aligned.m16n8k8.row.col.f32.tf32.tf32.f32 "
                        "{%0,%1,%2,%3}, {%4,%5,%6,%7}, {%8,%9}, {%0,%1,%2,%3};"
                        : "+f"(acc[mi][ni][0]), "+f"(acc[mi][ni][1]),
                          "+f"(acc[mi][ni][2]), "+f"(acc[mi][ni][3])
                        : "r"(a[mi][0]), "r"(a[mi][1]), "r"(a[mi][2]), "r"(a[mi][3]),
                          "r"(b[ni][0]), "r"(b[ni][1]));
                }
        }
    }

#pragma unroll
    for (int mi = 0; mi < 4; mi++) {
        size_t r = row0 + wm + mi * 16 + g;
#pragma unroll
        for (int ni = 0; ni < 4; ni++) {
            int c = col0 + wn + ni * 8 + tig * 2;
            float bx = 0.f, by = 0.f;
            if (bias) { bx = bias[c]; by = bias[c + 1]; }
            float o0 = acc[mi][ni][0] * alpha + bx;
            float o1 = acc[mi][ni][1] * alpha + by;
            float o2 = acc[mi][ni][2] * alpha + bx;
            float o3 = acc[mi][ni][3] * alpha + by;
            if (cvt_out) {
                o0 = f2tff(o0); o1 = f2tff(o1); o2 = f2tff(o2); o3 = f2tff(o3);
            }
            *(float2*)&Cm[r * ldc + c] = make_float2(o0, o1);
            *(float2*)&Cm[(r + 8) * ldc + c] = make_float2(o2, o3);
        }
    }
}

// ---------------- softmax (rows of 512), tf32-rounded output ---------------
__global__ void __launch_bounds__(256)
softmax_kernel(float* __restrict__ S) {
    float* r = S + (size_t)blockIdx.x * Ndim;
    int tid = threadIdx.x;
    float v0 = r[tid], v1 = r[tid + 256];
    __shared__ float red[8];
    unsigned full = 0xffffffffu;
    float m = fmaxf(v0, v1);
#pragma unroll
    for (int o = 16; o; o >>= 1) m = fmaxf(m, __shfl_xor_sync(full, m, o));
    if ((tid & 31) == 0) red[tid >> 5] = m;
    __syncthreads();
    float mm = fmaxf(fmaxf(fmaxf(red[0], red[1]), fmaxf(red[2], red[3])),
                     fmaxf(fmaxf(red[4], red[5]), fmaxf(red[6], red[7])));
    __syncthreads();
    float e0 = __expf(v0 - mm), e1 = __expf(v1 - mm);
    float s = e0 + e1;
#pragma unroll
    for (int o = 16; o; o >>= 1) s += __shfl_xor_sync(full, s, o);
    if ((tid & 31) == 0) red[tid >> 5] = s;
    __syncthreads();
    float inv = 1.0f / (red[0]+red[1]+red[2]+red[3]+red[4]+red[5]+red[6]+red[7]);
    r[tid] = f2tff(e0 * inv);
    r[tid + 256] = f2tff(e1 * inv);
}

// ---------------------------------------------------------------------------
extern "C" void kernel_launch(void* const* d_in, const int* in_sizes, int n_in,
                              void* d_out, int out_size) {
    const float* x     = (const float*)d_in[0];
    const float* mask  = (const float*)d_in[1];
    const float* Wqkv  = (const float*)d_in[4];
    const float* Wproj = (const float*)d_in[5];
    const float* bproj = (const float*)d_in[6];
    float* out = (float*)d_out;

    float* sc = nullptr;
    cudaGetSymbolAddress((void**)&sc, g_scratch);
    float* xq = sc + OFF_XQ;
    float* xk = sc + OFF_XK;
    float* Qb = sc + OFF_Q;
    float* Kb = sc + OFF_K;
    float* Vb = sc + OFF_V;
    float* Sb = sc + OFF_S;
    float* O2 = sc + OFF_O2;
    float* xc = sc + OFF_XC;
    float* Wc = sc + OFF_WC;
    float* Wp = sc + OFF_WP;

    const size_t sNC = (size_t)BN * Cdim;           // 2097152
    const size_t sNN = (size_t)Ndim * Ndim;         // 262144
    const size_t sNE = (size_t)Ndim * EP;           // 524288
    const size_t sVB = (size_t)Ndim * Pdim * Cdim;  // 4194304
    const int SMB = SMEM_WORDS * 4;                 // 71680 B

    cudaFuncSetAttribute(tgemm_kernel<0,0>, cudaFuncAttributeMaxDynamicSharedMemorySize, SMB);
    cudaFuncSetAttribute(tgemm_kernel<0,1>, cudaFuncAttributeMaxDynamicSharedMemorySize, SMB);
    cudaFuncSetAttribute(tgemm_kernel<0,2>, cudaFuncAttributeMaxDynamicSharedMemorySize, SMB);
    cudaFuncSetAttribute(tgemm_kernel<1,0>, cudaFuncAttributeMaxDynamicSharedMemorySize, SMB);

    // 0. tf32-convert weights
    cvt_copy_kernel<<<(Cdim * 3 * Cdim + 255) / 256, 256>>>(Wqkv, Wc, Cdim * 3 * Cdim);
    cvt_copy_kernel<<<(Cdim * Cdim + 255) / 256, 256>>>(Wproj, Wp, Cdim * Cdim);

    // 1. prep: xq/xk (converted) + converted x copy
    prep_kernel<<<BN, Cdim>>>(x, mask, xq, xk, xc);

    // 2. Q and K fused (z=0: xq@Wq -> Qb, z=1: xk@Wk -> Kb); outputs tf32
    tgemm_kernel<0,0><<<dim3(4, 32, 2), 256, SMB>>>(
        xq, Cdim, 0, sNC, Wc, 3 * Cdim, 0, 512, Qb, Cdim, 0, sNC,
        Cdim, 1.f, nullptr, 1);

    // 3. V = xc @ Wv; output tf32
    tgemm_kernel<0,0><<<dim3(4, BNP / 128, 1), 256, SMB>>>(
        xc, Cdim, 0, 0, Wc + 2 * Cdim, 3 * Cdim, 0, 0, Vb, Cdim, 0, 0,
        Cdim, 1.f, nullptr, 1);

    // 4. scores: S = 0.125 * Q @ K^T  (BT mode, K=64, per bh); fp32 out
    tgemm_kernel<0,2><<<dim3(4, 4, BH), 256, SMB>>>(
        Qb, Cdim, (size_t)Ndim * Cdim, HD,
        Kb, Cdim, (size_t)Ndim * Cdim, HD,
        Sb, Ndim, 8 * sNN, sNN,
        HD, 0.125f, nullptr, 0);

    // 5. softmax (tf32-rounded output)
    softmax_kernel<<<BH * Ndim, 256>>>(Sb);

    // 6. O2[bh][n][p*64+d] = S @ Vgather  (K=512, N=1024, per bh); tf32 out
    tgemm_kernel<0,1><<<dim3(8, 4, BH), 256, SMB>>>(
        Sb, Ndim, 8 * sNN, sNN,
        Vb, 0, sVB, (size_t)HD,
        O2, EP, 8 * sNE, sNE,
        Ndim, 1.f, nullptr, 1);

    // 7. proj: out = Ogather @ Wp + bproj; fp32 out
    tgemm_kernel<1,0><<<dim3(4, BNP / 128, 1), 256, SMB>>>(
        O2, 0, 0, 0, Wp, Cdim, 0, 0, out, Cdim, 0, 0,
        Cdim, 1.f, bproj, 0);
}

// round 12
// speedup vs baseline: 1.5565x; 1.0295x over previous
#include <cuda_runtime.h>
#include <cstdint>

#define Bdim 8
#define Ndim 512
#define Pdim 16
#define Cdim 512
#define HD   64
#define BN   (Bdim*Ndim)
#define BNP  (BN*Pdim)
#define BH   (Bdim*8)
#define EP   (HD*Pdim)

#define OFF_XQ 0ull
#define OFF_XK (OFF_XQ + (size_t)BN*Cdim)
#define OFF_Q  (OFF_XK + (size_t)BN*Cdim)
#define OFF_K  (OFF_Q  + (size_t)BN*Cdim)
#define OFF_V  (OFF_K  + (size_t)BN*Cdim)
#define OFF_S  (OFF_V  + (size_t)BNP*Cdim)
#define OFF_O2 (OFF_S  + (size_t)BH*Ndim*Ndim)
#define OFF_XC (OFF_O2 + (size_t)BNP*Cdim)
#define OFF_WC (OFF_XC + (size_t)BNP*Cdim)
#define OFF_WP (OFF_WC + (size_t)Cdim*3*Cdim)
#define SCRATCH_FLOATS (OFF_WP + (size_t)Cdim*Cdim)

__device__ float g_scratch[SCRATCH_FLOATS];

__device__ __forceinline__ uint32_t f2tf(float f) {
    uint32_t u;
    asm("cvt.rna.tf32.f32 %0, %1;" : "=r"(u) : "f"(f));
    return u;
}
__device__ __forceinline__ float f2tff(float f) { return __uint_as_float(f2tf(f)); }

__device__ __forceinline__ void cp16(uint32_t dst, const void* src) {
    asm volatile("cp.async.ca.shared.global [%0], [%1], 16;" :: "r"(dst), "l"(src));
}
__device__ __forceinline__ void cp_commit() {
    asm volatile("cp.async.commit_group;");
}
__device__ __forceinline__ void cp_wait0() {
    asm volatile("cp.async.wait_group 0;");
}

// dynamic smem layout (uint32 words):
//   As stage s: [s*4608 .. +4608)   (128 rows x 36; row stride 144B)
//   Bs stage s: [9216 + s*4352 ..)  (32 rows x 136)
#define ASTG 4608
#define BBASE 9216
#define BSTG 4352
#define SMEM_WORDS (BBASE + 2*BSTG)   /* 71680 B */

// ---------------- prep: xq/xk (tf32-rounded) + converted copy of x ---------
__global__ void prep_kernel(const float* __restrict__ x,
                            const float* __restrict__ mask,
                            float* __restrict__ xq, float* __restrict__ xk,
                            float* __restrict__ xc) {
    int bn = blockIdx.x, c = threadIdx.x;
    const float* xb = x + (size_t)bn * Pdim * Cdim;
    float* xcb = xc + (size_t)bn * Pdim * Cdim;
    const float* mb = mask + (size_t)bn * Pdim;
    float cnt = 0.f, s = 0.f;
#pragma unroll
    for (int p = 0; p < Pdim; p++) {
        float m = mb[p];
        float v = xb[(size_t)p * Cdim + c];
        cnt += m;
        s += m * v;
        xcb[(size_t)p * Cdim + c] = f2tff(v);
    }
    xq[(size_t)bn * Cdim + c] = f2tff(xb[c]);
    xk[(size_t)bn * Cdim + c] = f2tff(s / cnt);
}

// ---------------- elementwise tf32 convert copy ----------------------------
__global__ void cvt_copy_kernel(const float* __restrict__ src,
                                float* __restrict__ dst, int n) {
    int i = blockIdx.x * 256 + threadIdx.x;
    if (i < n) dst[i] = f2tff(src[i]);
}

// ---------------- tf32 tensor GEMM, cp.async staging + ldmatrix A ----------
// 128x128 tile, BK=32, 256 threads (8 warps, 2x4 grid, 64x32 warp tile).
// All operands must be PRE-ROUNDED to tf32 (cvt at producers).
// AM: 0 = A row-major [M,K];       1 = gather A from O2[bh][n][p*64+d]
// BM: 0 = B row-major [K,N];       1 = gather B[k=m][n=p*64+d] from V
//     2 = B[k][n] = Bm[n*ldb + k]  (transposed; legacy LDG+cvt staging)
template<int AM, int BM>
__global__ void __launch_bounds__(256, 2)
tgemm_kernel(const float* __restrict__ A, int lda, size_t sAb, size_t sAh,
             const float* __restrict__ Bm, int ldb, size_t sBb, size_t sBh,
             float* __restrict__ Cm, int ldc, size_t sCb, size_t sCh,
             int K, float alpha, const float* __restrict__ bias, int cvt_out) {
    extern __shared__ uint32_t smw[];
    const uint32_t sbase = (uint32_t)__cvta_generic_to_shared(smw);
    const int zb = blockIdx.z >> 3, zh = blockIdx.z & 7;
    A  += (size_t)zb * sAb + (size_t)zh * sAh;
    Bm += (size_t)zb * sBb + (size_t)zh * sBh;
    Cm += (size_t)zb * sCb + (size_t)zh * sCh;

    const int tid  = threadIdx.x;
    const int lane = tid & 31, warp = tid >> 5;
    const int g    = lane >> 2, tig = lane & 3;
    const int wm   = (warp >> 2) * 64;
    const int wn   = (warp & 3) * 32;
    const size_t row0 = (size_t)blockIdx.y * 128;
    const int col0 = blockIdx.x * 128;

    float acc[4][4][4];
#pragma unroll
    for (int mi = 0; mi < 4; mi++)
#pragma unroll
        for (int ni = 0; ni < 4; ni++)
#pragma unroll
            for (int r = 0; r < 4; r++) acc[mi][ni][r] = 0.f;

    const int ar = tid >> 3;        // 0..31 (+32*i)
    const int ac = (tid & 7) * 4;   // 0..28 within BK
    const int br = tid >> 3;        // k-row 0..31
    const int bc = (tid & 7) * 4;   // 0..28 (+32*i)
    const int tn = tid & 127, tkh = tid >> 7;   // BT staging

    // ldmatrix per-lane source position (within the A tile of current stage):
    //   row = wm + 16*mi + a_lm_row ; k-word = ks*8 + a_lm_k
    const int a_lm_row = (lane & 7) + 8 * ((lane >> 3) & 1);
    const int a_lm_k   = 4 * (lane >> 4);

    size_t gaBase[4];
    if (AM == 1) {
#pragma unroll
        for (int i = 0; i < 4; i++) {
            size_t row = row0 + ar + 32 * i;
            int ab = (int)(row >> 13);
            int an = (int)(row >> 4) & 511;
            int ap = (int)row & 15;
            gaBase[i] = (((size_t)ab * 8) * 512 + an) * 1024 + (size_t)ap * 64;
        }
    }

    auto copyA = [&](int st, int k0) {
        uint32_t d0 = sbase + (st * ASTG) * 4;
#pragma unroll
        for (int i = 0; i < 4; i++) {
            uint32_t dst = d0 + ((ar + 32 * i) * 36 + ac) * 4;
            const float* src;
            if (AM == 0) {
                src = A + (row0 + ar + 32 * i) * lda + k0 + ac;
            } else {
                int k = k0 + ac;
                int h = k >> 6, d = k & 63;
                src = A + gaBase[i] + (size_t)h * (512 * 1024) + d;
            }
            cp16(dst, src);
        }
    };
    auto copyB = [&](int st, int k0) {
        uint32_t d0 = sbase + (BBASE + st * BSTG) * 4;
        if (BM == 0) {
#pragma unroll
            for (int i = 0; i < 4; i++)
                cp16(d0 + (br * 136 + bc + 32 * i) * 4,
                     Bm + (size_t)(k0 + br) * ldb + col0 + bc + 32 * i);
        } else if (BM == 1) {
#pragma unroll
            for (int i = 0; i < 4; i++) {
                int n = col0 + bc + 32 * i;
                int pp = n >> 6, dd = n & 63;
                cp16(d0 + (br * 136 + bc + 32 * i) * 4,
                     Bm + ((size_t)(k0 + br) * 16 + pp) * 512 + dd);
            }
        } else {
            uint32_t* Bs = smw + BBASE + st * BSTG;
            const float* bcol = Bm + (size_t)(col0 + tn) * ldb + k0 + 16 * tkh;
#pragma unroll
            for (int i = 0; i < 4; i++) {
                float4 v = *(const float4*)(bcol + 4 * i);
                int k = 16 * tkh + 4 * i;
                Bs[(k + 0) * 136 + tn] = f2tf(v.x);
                Bs[(k + 1) * 136 + tn] = f2tf(v.y);
                Bs[(k + 2) * 136 + tn] = f2tf(v.z);
                Bs[(k + 3) * 136 + tn] = f2tf(v.w);
            }
        }
    };

    copyA(0, 0); copyB(0, 0);
    cp_commit();

    const int K32 = K >> 5;
    for (int it = 0; it < K32; it++) {
        const int st = it & 1;
        cp_wait0();
        __syncthreads();

        const bool more = (it + 1 < K32);
        if (more) { copyA(st ^ 1, (it + 1) * 32); copyB(st ^ 1, (it + 1) * 32); }
        cp_commit();

        const uint32_t aBase = sbase + (st * ASTG) * 4;
        const uint32_t* Bs = smw + BBASE + st * BSTG;
#pragma unroll
        for (int ks = 0; ks < 4; ks++) {
            const int k8 = ks * 8;
            uint32_t a[4][4], b[4][2];
#pragma unroll
            for (int mi = 0; mi < 4; mi++) {
                uint32_t addr = aBase +
                    ((wm + 16 * mi + a_lm_row) * 36 + k8 + a_lm_k) * 4;
                asm volatile(
                    "ldmatrix.sync.aligned.m8n8.x4.shared.b16 {%0,%1,%2,%3}, [%4];"
                    : "=r"(a[mi][0]), "=r"(a[mi][1]),
                      "=r"(a[mi][2]), "=r"(a[mi][3])
                    : "r"(addr));
            }
#pragma unroll
            for (int ni = 0; ni < 4; ni++) {
                int n = wn + ni * 8 + g;
                b[ni][0] = Bs[(k8 + tig) * 136 + n];
                b[ni][1] = Bs[(k8 + tig + 4) * 136 + n];
            }
#pragma unroll
            for (int mi = 0; mi < 4; mi++)
#pragma unroll
                for (int ni = 0; ni < 4; ni++) {
                    asm volatile(
                        "mma.sync.aligned.m16n8k8.row.col.f32.tf32.tf32.f32 "
                        "{%0,%1,%2,%3}, {%4,%5,%6,%7}, {%8,%9}, {%0,%1,%2,%3};"
                        : "+f"(acc[mi][ni][0]), "+f"(acc[mi][ni][1]),
                          "+f"(acc[mi][ni][2]), "+f"(acc[mi][ni][3])
                        : "r"(a[mi][0]), "r"(a[mi][1]), "r"(a[mi][2]), "r"(a[mi][3]),
                          "r"(b[ni][0]), "r"(b[ni][1]));
                }
        }
    }

#pragma unroll
    for (int mi = 0; mi < 4; mi++) {
        size_t r = row0 + wm + mi * 16 + g;
#pragma unroll
        for (int ni = 0; ni < 4; ni++) {
            int c = col0 + wn + ni * 8 + tig * 2;
            float bx = 0.f, by = 0.f;
            if (bias) { bx = bias[c]; by = bias[c + 1]; }
            float o0 = acc[mi][ni][0] * alpha + bx;
            float o1 = acc[mi][ni][1] * alpha + by;
            float o2 = acc[mi][ni][2] * alpha + bx;
            float o3 = acc[mi][ni][3] * alpha + by;
            if (cvt_out) {
                o0 = f2tff(o0); o1 = f2tff(o1); o2 = f2tff(o2); o3 = f2tff(o3);
            }
            *(float2*)&Cm[r * ldc + c] = make_float2(o0, o1);
            *(float2*)&Cm[(r + 8) * ldc + c] = make_float2(o2, o3);
        }
    }
}

// ---------------- softmax (rows of 512), tf32-rounded output ---------------
__global__ void __launch_bounds__(256)
softmax_kernel(float* __restrict__ S) {
    float* r = S + (size_t)blockIdx.x * Ndim;
    int tid = threadIdx.x;
    float v0 = r[tid], v1 = r[tid + 256];
    __shared__ float red[8];
    unsigned full = 0xffffffffu;
    float m = fmaxf(v0, v1);
#pragma unroll
    for (int o = 16; o; o >>= 1) m = fmaxf(m, __shfl_xor_sync(full, m, o));
    if ((tid & 31) == 0) red[tid >> 5] = m;
    __syncthreads();
    float mm = fmaxf(fmaxf(fmaxf(red[0], red[1]), fmaxf(red[2], red[3])),
                     fmaxf(fmaxf(red[4], red[5]), fmaxf(red[6], red[7])));
    __syncthreads();
    float e0 = __expf(v0 - mm), e1 = __expf(v1 - mm);
    float s = e0 + e1;
#pragma unroll
    for (int o = 16; o; o >>= 1) s += __shfl_xor_sync(full, s, o);
    if ((tid & 31) == 0) red[tid >> 5] = s;
    __syncthreads();
    float inv = 1.0f / (red[0]+red[1]+red[2]+red[3]+red[4]+red[5]+red[6]+red[7]);
    r[tid] = f2tff(e0 * inv);
    r[tid + 256] = f2tff(e1 * inv);
}

// ---------------------------------------------------------------------------
extern "C" void kernel_launch(void* const* d_in, const int* in_sizes, int n_in,
                              void* d_out, int out_size) {
    const float* x     = (const float*)d_in[0];
    const float* mask  = (const float*)d_in[1];
    const float* Wqkv  = (const float*)d_in[4];
    const float* Wproj = (const float*)d_in[5];
    const float* bproj = (const float*)d_in[6];
    float* out = (float*)d_out;

    float* sc = nullptr;
    cudaGetSymbolAddress((void**)&sc, g_scratch);
    float* xq = sc + OFF_XQ;
    float* xk = sc + OFF_XK;
    float* Qb = sc + OFF_Q;
    float* Kb = sc + OFF_K;
    float* Vb = sc + OFF_V;
    float* Sb = sc + OFF_S;
    float* O2 = sc + OFF_O2;
    float* xc = sc + OFF_XC;
    float* Wc = sc + OFF_WC;
    float* Wp = sc + OFF_WP;

    const size_t sNC = (size_t)BN * Cdim;           // 2097152
    const size_t sNN = (size_t)Ndim * Ndim;         // 262144
    const size_t sNE = (size_t)Ndim * EP;           // 524288
    const size_t sVB = (size_t)Ndim * Pdim * Cdim;  // 4194304
    const int SMB = SMEM_WORDS * 4;                 // 71680 B

    cudaFuncSetAttribute(tgemm_kernel<0,0>, cudaFuncAttributeMaxDynamicSharedMemorySize, SMB);
    cudaFuncSetAttribute(tgemm_kernel<0,1>, cudaFuncAttributeMaxDynamicSharedMemorySize, SMB);
    cudaFuncSetAttribute(tgemm_kernel<0,2>, cudaFuncAttributeMaxDynamicSharedMemorySize, SMB);
    cudaFuncSetAttribute(tgemm_kernel<1,0>, cudaFuncAttributeMaxDynamicSharedMemorySize, SMB);

    // 0. tf32-convert weights
    cvt_copy_kernel<<<(Cdim * 3 * Cdim + 255) / 256, 256>>>(Wqkv, Wc, Cdim * 3 * Cdim);
    cvt_copy_kernel<<<(Cdim * Cdim + 255) / 256, 256>>>(Wproj, Wp, Cdim * Cdim);

    // 1. prep: xq/xk (converted) + converted x copy
    prep_kernel<<<BN, Cdim>>>(x, mask, xq, xk, xc);

    // 2. Q and K fused (z=0: xq@Wq -> Qb, z=1: xk@Wk -> Kb); outputs tf32
    tgemm_kernel<0,0><<<dim3(4, 32, 2), 256, SMB>>>(
        xq, Cdim, 0, sNC, Wc, 3 * Cdim, 0, 512, Qb, Cdim, 0, sNC,
        Cdim, 1.f, nullptr, 1);

    // 3. V = xc @ Wv; output tf32
    tgemm_kernel<0,0><<<dim3(4, BNP / 128, 1), 256, SMB>>>(
        xc, Cdim, 0, 0, Wc + 2 * Cdim, 3 * Cdim, 0, 0, Vb, Cdim, 0, 0,
        Cdim, 1.f, nullptr, 1);

    // 4. scores: S = 0.125 * Q @ K^T  (BT mode, K=64, per bh); fp32 out
    tgemm_kernel<0,2><<<dim3(4, 4, BH), 256, SMB>>>(
        Qb, Cdim, (size_t)Ndim * Cdim, HD,
        Kb, Cdim, (size_t)Ndim * Cdim, HD,
        Sb, Ndim, 8 * sNN, sNN,
        HD, 0.125f, nullptr, 0);

    // 5. softmax (tf32-rounded output)
    softmax_kernel<<<BH * Ndim, 256>>>(Sb);

    // 6. O2[bh][n][p*64+d] = S @ Vgather  (K=512, N=1024, per bh); tf32 out
    tgemm_kernel<0,1><<<dim3(8, 4, BH), 256, SMB>>>(
        Sb, Ndim, 8 * sNN, sNN,
        Vb, 0, sVB, (size_t)HD,
        O2, EP, 8 * sNE, sNE,
        Ndim, 1.f, nullptr, 1);

    // 7. proj: out = Ogather @ Wp + bproj; fp32 out
    tgemm_kernel<1,0><<<dim3(4, BNP / 128, 1), 256, SMB>>>(
        O2, 0, 0, 0, Wp, Cdim, 0, 0, out, Cdim, 0, 0,
        Cdim, 1.f, bproj, 0);
}